// round 16
// baseline (speedup 1.0000x reference)
#include <cuda_runtime.h>
#include <cuda_bf16.h>
#include <cuda_fp16.h>
#include <cuda_fp8.h>
#include <stdint.h>

// MLPTexture3D fused instant-NGP hashgrid (L=16, T=2^19) + MLP(32-32-32-9) + sigmoid.
// R16: R13 tables (fp8 records l<6, compact bf16 pairs l>=6) +
//      (a) __ldcg on hashed gathers (keep L1D for coarse record levels),
//      (b) MLP layer 0 fused into the gather loop (same accumulation order).

constexpr int NLVL = 16;
constexpr uint32_t TBL = 1u << 19;
constexpr uint32_t TBLMASK = TBL - 1u;
constexpr uint32_t PHALF = TBL / 2u;
constexpr uint32_t HASH_BASE = 6u * TBL;
constexpr uint32_t NPAIRS = 10u * PHALF;

constexpr uint32_t REC_CELLS = 1593992u;   // levels 0..5: R={16,24,34,49,71,102}
constexpr float ENC_S = 65536.0f;
constexpr float INV_S = 1.0f / 65536.0f;

__device__ __align__(16) uint2 gPairB[NPAIRS];    // 20 MB bf16 compact pair table
__device__ __align__(16) uint4 gRec[REC_CELLS];   // 25.5 MB fp8 cell records

struct __align__(16) KConsts {
    uint32_t w0p[512];
    uint32_t w1p[512];
    uint32_t w2[144];
    float A[3];
    float invA[3];
    float lo[9];
    float df[9];
};
__constant__ KConsts cc;
__device__ KConsts gStage;

__device__ __forceinline__ __nv_bfloat162 u2b(uint32_t u) {
    return *reinterpret_cast<__nv_bfloat162*>(&u);
}
__device__ __forceinline__ uint32_t b2u(__nv_bfloat162 b) {
    return *reinterpret_cast<uint32_t*>(&b);
}
__device__ __forceinline__ __half2 fp8x2_to_h2(uint32_t u16) {
    __half2_raw r = __nv_cvt_fp8x2_to_halfraw2((__nv_fp8x2_storage_t)u16, __NV_E4M3);
    return *reinterpret_cast<__half2*>(&r);
}
__device__ __forceinline__ uint32_t enc8(float v) {
    return (uint32_t)__nv_cvt_float_to_fp8(v * ENC_S, __NV_SATFINITE, __NV_E4M3);
}

__global__ void __launch_bounds__(256)
repack_pairs(const float2* __restrict__ grid)
{
    const uint32_t j = blockIdx.x * 256u + threadIdx.x;
    if (j >= NPAIRS) return;
    const float4 v = __ldcs(reinterpret_cast<const float4*>(grid)
                            + (HASH_BASE >> 1) + j);
    uint2 o;
    o.x = b2u(__floats2bfloat162_rn(v.x, v.y));
    o.y = b2u(__floats2bfloat162_rn(v.z, v.w));
    gPairB[j] = o;
}

__global__ void __launch_bounds__(256)
repack_records(const float2* __restrict__ grid)
{
    const uint32_t t = blockIdx.x * 256u + threadIdx.x;
    if (t >= REC_CELLS) return;

    int l; uint32_t cid;
    if      (t < 4096u)    { l = 0; cid = t; }
    else if (t < 17920u)   { l = 1; cid = t - 4096u; }
    else if (t < 57224u)   { l = 2; cid = t - 17920u; }
    else if (t < 174873u)  { l = 3; cid = t - 57224u; }
    else if (t < 532784u)  { l = 4; cid = t - 174873u; }
    else                   { l = 5; cid = t - 532784u; }
    const uint32_t R = (l == 0) ? 16u : (l == 1) ? 24u : (l == 2) ? 34u
                      : (l == 3) ? 49u : (l == 4) ? 71u : 102u;
    const uint32_t rm = R - 1u;
    const uint32_t ix = cid % R;
    const uint32_t tmp = cid / R;
    const uint32_t iy = tmp % R;
    const uint32_t iz = tmp / R;

    const float2* __restrict__ gl = grid + (size_t)l * TBL;
    uint32_t w[4];
#pragma unroll
    for (int jj = 0; jj < 4; ++jj) {
        uint32_t word = 0;
#pragma unroll
        for (int h = 0; h < 2; ++h) {
            const int c = 2 * jj + h;
            const uint32_t ox = (uint32_t)(c & 1);
            const uint32_t oy = (uint32_t)((c >> 1) & 1);
            const uint32_t oz = (uint32_t)(c >> 2);
            uint32_t idx;
            if (l < 5) {
                const uint32_t cx = min(ix + ox, rm);
                const uint32_t cy = min(iy + oy, rm);
                const uint32_t cz = min(iz + oz, rm);
                idx = cx + cy * R + cz * R * R;
            } else {
                const uint32_t cx = ix + ox, cy = iy + oy, cz = iz + oz;
                idx = (cx ^ (cy * 2654435761u) ^ (cz * 805459861u)) & TBLMASK;
            }
            const float2 v = gl[idx];
            word |= enc8(v.x) << (16 * h);
            word |= enc8(v.y) << (16 * h + 8);
        }
        w[jj] = word;
    }
    gRec[t] = make_uint4(w[0], w[1], w[2], w[3]);
}

__global__ void __launch_bounds__(256)
prep_consts(const float* __restrict__ W0, const float* __restrict__ W1,
            const float* __restrict__ W2, const float* __restrict__ AABB,
            const float* __restrict__ minmax)
{
    const int t = threadIdx.x;
    for (int idx = t; idx < 512; idx += 256) {
        const int s = idx >> 4;
        const int p = idx & 15;
        gStage.w0p[idx] = b2u(__floats2bfloat162_rn(W0[(2 * p) * 32 + s],
                                                    W0[(2 * p + 1) * 32 + s]));
        gStage.w1p[idx] = b2u(__floats2bfloat162_rn(W1[(2 * p) * 32 + s],
                                                    W1[(2 * p + 1) * 32 + s]));
    }
    if (t < 144)
        gStage.w2[t] = b2u(__floats2bfloat162_rn(W2[2 * t], W2[2 * t + 1]));
    if (t < 3) {
        gStage.A[t] = AABB[t];
        gStage.invA[t] = 1.0f / (AABB[3 + t] - AABB[t]);
    }
    if (t < 9) { float lo = minmax[t]; gStage.lo[t] = lo; gStage.df[t] = minmax[9 + t] - lo; }
}

__global__ void __launch_bounds__(256, 4)
fused_ngp_mlp(const float* __restrict__ texc,
              float* __restrict__ out,
              int N)
{
    __shared__ __align__(16) float sTex[768];
    __shared__ __align__(16) float sOut[2304];

    const int tid = threadIdx.x;
    const int base = blockIdx.x * 256;
    const bool fullBlock = (base + 256 <= N);

    if (fullBlock) {
        const float4* t4 = reinterpret_cast<const float4*>(texc + (size_t)base * 3);
        if (tid < 192) {
            const float4 v = __ldcs(t4 + tid);
            reinterpret_cast<float4*>(sTex)[tid] = v;
        }
    } else {
        const int cnt = (N - base) * 3;
        for (int i = tid; i < cnt; i += 256) sTex[i] = texc[(size_t)base * 3 + i];
    }
    __syncthreads();

    const int n = base + tid;
    if (n < N) {
        const float ux = __saturatef((sTex[3 * tid + 0] - cc.A[0]) * cc.invA[0]);
        const float uy = __saturatef((sTex[3 * tid + 1] - cc.A[1]) * cc.invA[1]);
        const float uz = __saturatef((sTex[3 * tid + 2] - cc.A[2]) * cc.invA[2]);

        const __nv_bfloat162 bz = __float2bfloat162_rn(0.0f);

        // Layer-0 accumulators, fed incrementally per level (same order as the
        // original s2 = 0..15 loop -> identical numerics).
        __nv_bfloat162 l0[16];
#pragma unroll
        for (int p = 0; p < 16; ++p) l0[p] = bz;

#pragma unroll
        for (int l = 0; l < NLVL; ++l) {
            const float scale = 16.0f * exp2f((float)l * (8.0f / 15.0f)) - 1.0f;
            const float posx = ux * scale + 0.5f;
            const float posy = uy * scale + 0.5f;
            const float posz = uz * scale + 0.5f;
            const float flx = floorf(posx), fly = floorf(posy), flz = floorf(posz);
            const float rx = posx - flx, ry = posy - fly, rz = posz - flz;
            const uint32_t ix = (uint32_t)flx, iy = (uint32_t)fly, iz = (uint32_t)flz;

            const float wx0 = 1.0f - rx, wy0 = 1.0f - ry, wz0 = 1.0f - rz;
            const float pw[4] = { wy0 * wz0, ry * wz0, wy0 * rz, ry * rz };

            __nv_bfloat162 x;   // this level's feature pair (bf16x2)
            if (l < 6) {
                // fp8 cell record: one LDG.128 (default policy: small levels L1-hit)
                const uint32_t R = (l == 0) ? 16u : (l == 1) ? 24u : (l == 2) ? 34u
                                  : (l == 3) ? 49u : (l == 4) ? 71u : 102u;
                const uint32_t recOff =
                    (l == 0) ? 0u : (l == 1) ? 4096u : (l == 2) ? 17920u
                  : (l == 3) ? 57224u : (l == 4) ? 174873u : 532784u;
                const uint32_t cid = ix + iy * R + iz * R * R;
                const uint4 q = __ldg(gRec + recOff + cid);

                __half2 acc = __float2half2_rn(0.0f);
                const uint32_t ws[4] = { q.x, q.y, q.z, q.w };
#pragma unroll
                for (int j = 0; j < 4; ++j) {
                    const __half2 ve = fp8x2_to_h2(ws[j] & 0xFFFFu);
                    const __half2 vo = fp8x2_to_h2(ws[j] >> 16);
                    acc = __hfma2(__float2half2_rn(pw[j] * wx0), ve, acc);
                    acc = __hfma2(__float2half2_rn(pw[j] * rx),  vo, acc);
                }
                const float2 fv = __half22float2(acc);
                x = __floats2bfloat162_rn(fv.x * INV_S, fv.y * INV_S);
            } else {
                // hashed: compact bf16 pair table, 4x 8B .cg gathers (bypass L1)
                const uint32_t hy0 = iy * 2654435761u, hy1 = hy0 + 2654435761u;
                const uint32_t hz0 = iz * 805459861u,  hz1 = hz0 + 805459861u;
                const uint32_t b00 = hy0 ^ hz0, b10 = hy1 ^ hz0;
                const uint32_t b01 = hy0 ^ hz1, b11 = hy1 ^ hz1;
                const uint32_t a0 = (ix ^ b00) & TBLMASK;
                const uint32_t a1 = (ix ^ b10) & TBLMASK;
                const uint32_t a2 = (ix ^ b01) & TBLMASK;
                const uint32_t a3 = (ix ^ b11) & TBLMASK;

                const uint2* __restrict__ pf = gPairB + (size_t)(l - 6) * PHALF;
                uint2 q[4];
                q[0] = __ldcg(pf + (a0 >> 1));
                q[1] = __ldcg(pf + (a1 >> 1));
                q[2] = __ldcg(pf + (a2 >> 1));
                q[3] = __ldcg(pf + (a3 >> 1));
                const uint32_t odd[4] = { a0 & 1u, a1 & 1u, a2 & 1u, a3 & 1u };

                __nv_bfloat162 facc = bz;
#pragma unroll
                for (int c = 0; c < 4; ++c) {
                    const float w0c = pw[c] * wx0;
                    const float w1c = pw[c] * rx;
                    const float we = odd[c] ? w1c : w0c;
                    const float wo = odd[c] ? w0c : w1c;
                    facc = __hfma2(__float2bfloat162_rn(we), u2b(q[c].x), facc);
                    facc = __hfma2(__float2bfloat162_rn(wo), u2b(q[c].y), facc);
                }
                x = facc;
            }

            // ---- fused MLP layer-0 contribution of level l ----
            {
                const __nv_bfloat162 xlo = __bfloat162bfloat162(__low2bfloat16(x));
                const __nv_bfloat162 xhi = __bfloat162bfloat162(__high2bfloat16(x));
                const uint4* wa = reinterpret_cast<const uint4*>(cc.w0p + (2 * l) * 16);
                const uint4* wb = reinterpret_cast<const uint4*>(cc.w0p + (2 * l + 1) * 16);
#pragma unroll
                for (int q = 0; q < 4; ++q) {
                    const uint4 A4 = wa[q];
                    const uint4 B4 = wb[q];
                    l0[4 * q + 0] = __hfma2(xlo, u2b(A4.x), l0[4 * q + 0]);
                    l0[4 * q + 1] = __hfma2(xlo, u2b(A4.y), l0[4 * q + 1]);
                    l0[4 * q + 2] = __hfma2(xlo, u2b(A4.z), l0[4 * q + 2]);
                    l0[4 * q + 3] = __hfma2(xlo, u2b(A4.w), l0[4 * q + 3]);
                    l0[4 * q + 0] = __hfma2(xhi, u2b(B4.x), l0[4 * q + 0]);
                    l0[4 * q + 1] = __hfma2(xhi, u2b(B4.y), l0[4 * q + 1]);
                    l0[4 * q + 2] = __hfma2(xhi, u2b(B4.z), l0[4 * q + 2]);
                    l0[4 * q + 3] = __hfma2(xhi, u2b(B4.w), l0[4 * q + 3]);
                }
            }
        }

        // ---- ReLU layer 0 ----
        __nv_bfloat162 hp[16];
#pragma unroll
        for (int p = 0; p < 16; ++p) hp[p] = __hmax2(l0[p], bz);

        // ---- MLP layer 1 ----
        __nv_bfloat162 h2p[16];
        {
            __nv_bfloat162 acc[16];
#pragma unroll
            for (int p = 0; p < 16; ++p) acc[p] = bz;
#pragma unroll
            for (int s2 = 0; s2 < 16; ++s2) {
                const __nv_bfloat162 x = hp[s2];
                const __nv_bfloat162 xlo = __bfloat162bfloat162(__low2bfloat16(x));
                const __nv_bfloat162 xhi = __bfloat162bfloat162(__high2bfloat16(x));
                const uint4* wa = reinterpret_cast<const uint4*>(cc.w1p + (2 * s2) * 16);
                const uint4* wb = reinterpret_cast<const uint4*>(cc.w1p + (2 * s2 + 1) * 16);
#pragma unroll
                for (int q = 0; q < 4; ++q) {
                    const uint4 A4 = wa[q];
                    const uint4 B4 = wb[q];
                    acc[4 * q + 0] = __hfma2(xlo, u2b(A4.x), acc[4 * q + 0]);
                    acc[4 * q + 1] = __hfma2(xlo, u2b(A4.y), acc[4 * q + 1]);
                    acc[4 * q + 2] = __hfma2(xlo, u2b(A4.z), acc[4 * q + 2]);
                    acc[4 * q + 3] = __hfma2(xlo, u2b(A4.w), acc[4 * q + 3]);
                    acc[4 * q + 0] = __hfma2(xhi, u2b(B4.x), acc[4 * q + 0]);
                    acc[4 * q + 1] = __hfma2(xhi, u2b(B4.y), acc[4 * q + 1]);
                    acc[4 * q + 2] = __hfma2(xhi, u2b(B4.z), acc[4 * q + 2]);
                    acc[4 * q + 3] = __hfma2(xhi, u2b(B4.w), acc[4 * q + 3]);
                }
            }
#pragma unroll
            for (int p = 0; p < 16; ++p) h2p[p] = __hmax2(acc[p], bz);
        }

        // ---- MLP layer 2 (row-wise) + sigmoid + scale -> SMEM stage ----
#pragma unroll
        for (int k = 0; k < 9; ++k) {
            const uint4* wr = reinterpret_cast<const uint4*>(cc.w2 + k * 16);
            __nv_bfloat162 acc0 = bz;
            __nv_bfloat162 acc1 = bz;
#pragma unroll
            for (int i = 0; i < 4; ++i) {
                const uint4 w = wr[i];
                acc0 = __hfma2(h2p[4 * i + 0], u2b(w.x), acc0);
                acc1 = __hfma2(h2p[4 * i + 1], u2b(w.y), acc1);
                acc0 = __hfma2(h2p[4 * i + 2], u2b(w.z), acc0);
                acc1 = __hfma2(h2p[4 * i + 3], u2b(w.w), acc1);
            }
            const float o = __low2float(acc0) + __high2float(acc0)
                          + __low2float(acc1) + __high2float(acc1);
            const float sig = 1.0f / (1.0f + __expf(-o));
            sOut[tid * 9 + k] = fmaf(sig, cc.df[k], cc.lo[k]);
        }
    }
    __syncthreads();

    if (fullBlock) {
        float4* o4 = reinterpret_cast<float4*>(out + (size_t)base * 9);
        const float4* s4 = reinterpret_cast<const float4*>(sOut);
#pragma unroll
        for (int i = 0; i < 3; ++i) {
            const int idx = tid + 256 * i;
            if (idx < 576) __stcs(o4 + idx, s4[idx]);
        }
    } else {
        const int cnt = (N - base) * 9;
        for (int i = tid; i < cnt; i += 256) out[(size_t)base * 9 + i] = sOut[i];
    }
}

extern "C" void kernel_launch(void* const* d_in, const int* in_sizes, int n_in,
                              void* d_out, int out_size) {
    const float* texc   = (const float*)d_in[0];
    const float* grid   = (const float*)d_in[1];
    const float* W0     = (const float*)d_in[2];
    const float* W1     = (const float*)d_in[3];
    const float* W2     = (const float*)d_in[4];
    const float* AABB   = (const float*)d_in[5];
    const float* minmax = (const float*)d_in[6];
    float* out = (float*)d_out;

    const int N = in_sizes[0] / 3;

    repack_pairs<<<(NPAIRS + 255u) / 256u, 256>>>(
        reinterpret_cast<const float2*>(grid));
    repack_records<<<(REC_CELLS + 255u) / 256u, 256>>>(
        reinterpret_cast<const float2*>(grid));
    prep_consts<<<1, 256>>>(W0, W1, W2, AABB, minmax);

    void* stagePtr = nullptr;
    cudaGetSymbolAddress(&stagePtr, gStage);
    cudaMemcpyToSymbolAsync(cc, stagePtr, sizeof(KConsts), 0,
                            cudaMemcpyDeviceToDevice, 0);

    const int blocks = (N + 255) / 256;
    fused_ngp_mlp<<<blocks, 256>>>(texc, out, N);
}

// round 17
// speedup vs baseline: 1.1577x; 1.1577x over previous
#include <cuda_runtime.h>
#include <cuda_bf16.h>
#include <cuda_fp16.h>
#include <cuda_fp8.h>
#include <stdint.h>

// MLPTexture3D fused instant-NGP hashgrid (L=16, T=2^19) + MLP(32-32-32-9) + sigmoid.
// R17: exactly R13 (819.3us champion) + ONE change: hashed pair gathers use
//      __ldcg (L2-only) so L1D retains the small coarse record levels.

constexpr int NLVL = 16;
constexpr uint32_t TBL = 1u << 19;
constexpr uint32_t TBLMASK = TBL - 1u;
constexpr uint32_t PHALF = TBL / 2u;
constexpr uint32_t HASH_BASE = 6u * TBL;
constexpr uint32_t NPAIRS = 10u * PHALF;

constexpr uint32_t REC_CELLS = 1593992u;   // levels 0..5: R={16,24,34,49,71,102}
constexpr float ENC_S = 65536.0f;
constexpr float INV_S = 1.0f / 65536.0f;

__device__ __align__(16) uint2 gPairB[NPAIRS];    // 20 MB bf16 compact pair table
__device__ __align__(16) uint4 gRec[REC_CELLS];   // 25.5 MB fp8 cell records

struct __align__(16) KConsts {
    uint32_t w0p[512];
    uint32_t w1p[512];
    uint32_t w2[144];
    float A[3];
    float invA[3];
    float lo[9];
    float df[9];
};
__constant__ KConsts cc;
__device__ KConsts gStage;

__device__ __forceinline__ __nv_bfloat162 u2b(uint32_t u) {
    return *reinterpret_cast<__nv_bfloat162*>(&u);
}
__device__ __forceinline__ uint32_t b2u(__nv_bfloat162 b) {
    return *reinterpret_cast<uint32_t*>(&b);
}
__device__ __forceinline__ __half2 fp8x2_to_h2(uint32_t u16) {
    __half2_raw r = __nv_cvt_fp8x2_to_halfraw2((__nv_fp8x2_storage_t)u16, __NV_E4M3);
    return *reinterpret_cast<__half2*>(&r);
}
__device__ __forceinline__ uint32_t enc8(float v) {
    return (uint32_t)__nv_cvt_float_to_fp8(v * ENC_S, __NV_SATFINITE, __NV_E4M3);
}

__global__ void __launch_bounds__(256)
repack_pairs(const float2* __restrict__ grid)
{
    const uint32_t j = blockIdx.x * 256u + threadIdx.x;
    if (j >= NPAIRS) return;
    const float4 v = __ldcs(reinterpret_cast<const float4*>(grid)
                            + (HASH_BASE >> 1) + j);
    uint2 o;
    o.x = b2u(__floats2bfloat162_rn(v.x, v.y));
    o.y = b2u(__floats2bfloat162_rn(v.z, v.w));
    gPairB[j] = o;
}

__global__ void __launch_bounds__(256)
repack_records(const float2* __restrict__ grid)
{
    const uint32_t t = blockIdx.x * 256u + threadIdx.x;
    if (t >= REC_CELLS) return;

    int l; uint32_t cid;
    if      (t < 4096u)    { l = 0; cid = t; }
    else if (t < 17920u)   { l = 1; cid = t - 4096u; }
    else if (t < 57224u)   { l = 2; cid = t - 17920u; }
    else if (t < 174873u)  { l = 3; cid = t - 57224u; }
    else if (t < 532784u)  { l = 4; cid = t - 174873u; }
    else                   { l = 5; cid = t - 532784u; }
    const uint32_t R = (l == 0) ? 16u : (l == 1) ? 24u : (l == 2) ? 34u
                      : (l == 3) ? 49u : (l == 4) ? 71u : 102u;
    const uint32_t rm = R - 1u;
    const uint32_t ix = cid % R;
    const uint32_t tmp = cid / R;
    const uint32_t iy = tmp % R;
    const uint32_t iz = tmp / R;

    const float2* __restrict__ gl = grid + (size_t)l * TBL;
    uint32_t w[4];
#pragma unroll
    for (int jj = 0; jj < 4; ++jj) {
        uint32_t word = 0;
#pragma unroll
        for (int h = 0; h < 2; ++h) {
            const int c = 2 * jj + h;          // corner id = x + 2y + 4z
            const uint32_t ox = (uint32_t)(c & 1);
            const uint32_t oy = (uint32_t)((c >> 1) & 1);
            const uint32_t oz = (uint32_t)(c >> 2);
            uint32_t idx;
            if (l < 5) {
                const uint32_t cx = min(ix + ox, rm);
                const uint32_t cy = min(iy + oy, rm);
                const uint32_t cz = min(iz + oz, rm);
                idx = cx + cy * R + cz * R * R;
            } else {
                const uint32_t cx = ix + ox, cy = iy + oy, cz = iz + oz;
                idx = (cx ^ (cy * 2654435761u) ^ (cz * 805459861u)) & TBLMASK;
            }
            const float2 v = gl[idx];
            word |= enc8(v.x) << (16 * h);
            word |= enc8(v.y) << (16 * h + 8);
        }
        w[jj] = word;
    }
    gRec[t] = make_uint4(w[0], w[1], w[2], w[3]);
}

__global__ void __launch_bounds__(256)
prep_consts(const float* __restrict__ W0, const float* __restrict__ W1,
            const float* __restrict__ W2, const float* __restrict__ AABB,
            const float* __restrict__ minmax)
{
    const int t = threadIdx.x;
    for (int idx = t; idx < 512; idx += 256) {
        const int s = idx >> 4;
        const int p = idx & 15;
        gStage.w0p[idx] = b2u(__floats2bfloat162_rn(W0[(2 * p) * 32 + s],
                                                    W0[(2 * p + 1) * 32 + s]));
        gStage.w1p[idx] = b2u(__floats2bfloat162_rn(W1[(2 * p) * 32 + s],
                                                    W1[(2 * p + 1) * 32 + s]));
    }
    if (t < 144)
        gStage.w2[t] = b2u(__floats2bfloat162_rn(W2[2 * t], W2[2 * t + 1]));
    if (t < 3) {
        gStage.A[t] = AABB[t];
        gStage.invA[t] = 1.0f / (AABB[3 + t] - AABB[t]);
    }
    if (t < 9) { float lo = minmax[t]; gStage.lo[t] = lo; gStage.df[t] = minmax[9 + t] - lo; }
}

__global__ void __launch_bounds__(256, 4)
fused_ngp_mlp(const float* __restrict__ texc,
              float* __restrict__ out,
              int N)
{
    __shared__ __align__(16) float sTex[768];
    __shared__ __align__(16) float sOut[2304];

    const int tid = threadIdx.x;
    const int base = blockIdx.x * 256;
    const bool fullBlock = (base + 256 <= N);

    if (fullBlock) {
        const float4* t4 = reinterpret_cast<const float4*>(texc + (size_t)base * 3);
        if (tid < 192) {
            const float4 v = __ldcs(t4 + tid);
            reinterpret_cast<float4*>(sTex)[tid] = v;
        }
    } else {
        const int cnt = (N - base) * 3;
        for (int i = tid; i < cnt; i += 256) sTex[i] = texc[(size_t)base * 3 + i];
    }
    __syncthreads();

    const int n = base + tid;
    if (n < N) {
        const float ux = __saturatef((sTex[3 * tid + 0] - cc.A[0]) * cc.invA[0]);
        const float uy = __saturatef((sTex[3 * tid + 1] - cc.A[1]) * cc.invA[1]);
        const float uz = __saturatef((sTex[3 * tid + 2] - cc.A[2]) * cc.invA[2]);

        __nv_bfloat162 fp[16];

#pragma unroll
        for (int l = 0; l < NLVL; ++l) {
            const float scale = 16.0f * exp2f((float)l * (8.0f / 15.0f)) - 1.0f;
            const float posx = ux * scale + 0.5f;
            const float posy = uy * scale + 0.5f;
            const float posz = uz * scale + 0.5f;
            const float flx = floorf(posx), fly = floorf(posy), flz = floorf(posz);
            const float rx = posx - flx, ry = posy - fly, rz = posz - flz;
            const uint32_t ix = (uint32_t)flx, iy = (uint32_t)fly, iz = (uint32_t)flz;

            const float wx0 = 1.0f - rx, wy0 = 1.0f - ry, wz0 = 1.0f - rz;
            const float pw[4] = { wy0 * wz0, ry * wz0, wy0 * rz, ry * rz };

            if (l < 6) {
                // fp8 cell record: one LDG.128 (default policy; small levels L1-hit)
                const uint32_t R = (l == 0) ? 16u : (l == 1) ? 24u : (l == 2) ? 34u
                                  : (l == 3) ? 49u : (l == 4) ? 71u : 102u;
                const uint32_t recOff =
                    (l == 0) ? 0u : (l == 1) ? 4096u : (l == 2) ? 17920u
                  : (l == 3) ? 57224u : (l == 4) ? 174873u : 532784u;
                const uint32_t cid = ix + iy * R + iz * R * R;
                const uint4 q = __ldg(gRec + recOff + cid);

                __half2 acc = __float2half2_rn(0.0f);
                const uint32_t ws[4] = { q.x, q.y, q.z, q.w };
#pragma unroll
                for (int j = 0; j < 4; ++j) {
                    const __half2 ve = fp8x2_to_h2(ws[j] & 0xFFFFu);
                    const __half2 vo = fp8x2_to_h2(ws[j] >> 16);
                    acc = __hfma2(__float2half2_rn(pw[j] * wx0), ve, acc);
                    acc = __hfma2(__float2half2_rn(pw[j] * rx),  vo, acc);
                }
                const float2 fv = __half22float2(acc);
                fp[l] = __floats2bfloat162_rn(fv.x * INV_S, fv.y * INV_S);
            } else {
                // hashed: compact bf16 pair table, 4x 8B gathers, L2-only (.cg)
                const uint32_t hy0 = iy * 2654435761u, hy1 = hy0 + 2654435761u;
                const uint32_t hz0 = iz * 805459861u,  hz1 = hz0 + 805459861u;
                const uint32_t b00 = hy0 ^ hz0, b10 = hy1 ^ hz0;
                const uint32_t b01 = hy0 ^ hz1, b11 = hy1 ^ hz1;
                const uint32_t a0 = (ix ^ b00) & TBLMASK;
                const uint32_t a1 = (ix ^ b10) & TBLMASK;
                const uint32_t a2 = (ix ^ b01) & TBLMASK;
                const uint32_t a3 = (ix ^ b11) & TBLMASK;

                const uint2* __restrict__ pf = gPairB + (size_t)(l - 6) * PHALF;
                uint2 q[4];
                q[0] = __ldcg(pf + (a0 >> 1));
                q[1] = __ldcg(pf + (a1 >> 1));
                q[2] = __ldcg(pf + (a2 >> 1));
                q[3] = __ldcg(pf + (a3 >> 1));
                const uint32_t odd[4] = { a0 & 1u, a1 & 1u, a2 & 1u, a3 & 1u };

                __nv_bfloat162 facc = __float2bfloat162_rn(0.0f);
#pragma unroll
                for (int c = 0; c < 4; ++c) {
                    const float w0c = pw[c] * wx0;
                    const float w1c = pw[c] * rx;
                    const float we = odd[c] ? w1c : w0c;
                    const float wo = odd[c] ? w0c : w1c;
                    facc = __hfma2(__float2bfloat162_rn(we), u2b(q[c].x), facc);
                    facc = __hfma2(__float2bfloat162_rn(wo), u2b(q[c].y), facc);
                }
                fp[l] = facc;
            }
        }

        const __nv_bfloat162 bz = __float2bfloat162_rn(0.0f);

        // ---- MLP layer 0: packed output-pair accumulation ----
        __nv_bfloat162 hp[16];
        {
            __nv_bfloat162 acc[16];
#pragma unroll
            for (int p = 0; p < 16; ++p) acc[p] = bz;
#pragma unroll
            for (int s2 = 0; s2 < 16; ++s2) {
                const __nv_bfloat162 x = fp[s2];
                const __nv_bfloat162 xlo = __bfloat162bfloat162(__low2bfloat16(x));
                const __nv_bfloat162 xhi = __bfloat162bfloat162(__high2bfloat16(x));
                const uint4* wa = reinterpret_cast<const uint4*>(cc.w0p + (2 * s2) * 16);
                const uint4* wb = reinterpret_cast<const uint4*>(cc.w0p + (2 * s2 + 1) * 16);
#pragma unroll
                for (int q = 0; q < 4; ++q) {
                    const uint4 A4 = wa[q];
                    const uint4 B4 = wb[q];
                    acc[4 * q + 0] = __hfma2(xlo, u2b(A4.x), acc[4 * q + 0]);
                    acc[4 * q + 1] = __hfma2(xlo, u2b(A4.y), acc[4 * q + 1]);
                    acc[4 * q + 2] = __hfma2(xlo, u2b(A4.z), acc[4 * q + 2]);
                    acc[4 * q + 3] = __hfma2(xlo, u2b(A4.w), acc[4 * q + 3]);
                    acc[4 * q + 0] = __hfma2(xhi, u2b(B4.x), acc[4 * q + 0]);
                    acc[4 * q + 1] = __hfma2(xhi, u2b(B4.y), acc[4 * q + 1]);
                    acc[4 * q + 2] = __hfma2(xhi, u2b(B4.z), acc[4 * q + 2]);
                    acc[4 * q + 3] = __hfma2(xhi, u2b(B4.w), acc[4 * q + 3]);
                }
            }
#pragma unroll
            for (int p = 0; p < 16; ++p) hp[p] = __hmax2(acc[p], bz);
        }

        // ---- MLP layer 1 ----
        __nv_bfloat162 h2p[16];
        {
            __nv_bfloat162 acc[16];
#pragma unroll
            for (int p = 0; p < 16; ++p) acc[p] = bz;
#pragma unroll
            for (int s2 = 0; s2 < 16; ++s2) {
                const __nv_bfloat162 x = hp[s2];
                const __nv_bfloat162 xlo = __bfloat162bfloat162(__low2bfloat16(x));
                const __nv_bfloat162 xhi = __bfloat162bfloat162(__high2bfloat16(x));
                const uint4* wa = reinterpret_cast<const uint4*>(cc.w1p + (2 * s2) * 16);
                const uint4* wb = reinterpret_cast<const uint4*>(cc.w1p + (2 * s2 + 1) * 16);
#pragma unroll
                for (int q = 0; q < 4; ++q) {
                    const uint4 A4 = wa[q];
                    const uint4 B4 = wb[q];
                    acc[4 * q + 0] = __hfma2(xlo, u2b(A4.x), acc[4 * q + 0]);
                    acc[4 * q + 1] = __hfma2(xlo, u2b(A4.y), acc[4 * q + 1]);
                    acc[4 * q + 2] = __hfma2(xlo, u2b(A4.z), acc[4 * q + 2]);
                    acc[4 * q + 3] = __hfma2(xlo, u2b(A4.w), acc[4 * q + 3]);
                    acc[4 * q + 0] = __hfma2(xhi, u2b(B4.x), acc[4 * q + 0]);
                    acc[4 * q + 1] = __hfma2(xhi, u2b(B4.y), acc[4 * q + 1]);
                    acc[4 * q + 2] = __hfma2(xhi, u2b(B4.z), acc[4 * q + 2]);
                    acc[4 * q + 3] = __hfma2(xhi, u2b(B4.w), acc[4 * q + 3]);
                }
            }
#pragma unroll
            for (int p = 0; p < 16; ++p) h2p[p] = __hmax2(acc[p], bz);
        }

        // ---- MLP layer 2 (row-wise) + sigmoid + scale -> SMEM stage ----
#pragma unroll
        for (int k = 0; k < 9; ++k) {
            const uint4* wr = reinterpret_cast<const uint4*>(cc.w2 + k * 16);
            __nv_bfloat162 acc0 = bz;
            __nv_bfloat162 acc1 = bz;
#pragma unroll
            for (int i = 0; i < 4; ++i) {
                const uint4 w = wr[i];
                acc0 = __hfma2(h2p[4 * i + 0], u2b(w.x), acc0);
                acc1 = __hfma2(h2p[4 * i + 1], u2b(w.y), acc1);
                acc0 = __hfma2(h2p[4 * i + 2], u2b(w.z), acc0);
                acc1 = __hfma2(h2p[4 * i + 3], u2b(w.w), acc1);
            }
            const float o = __low2float(acc0) + __high2float(acc0)
                          + __low2float(acc1) + __high2float(acc1);
            const float sig = 1.0f / (1.0f + __expf(-o));
            sOut[tid * 9 + k] = fmaf(sig, cc.df[k], cc.lo[k]);
        }
    }
    __syncthreads();

    if (fullBlock) {
        float4* o4 = reinterpret_cast<float4*>(out + (size_t)base * 9);
        const float4* s4 = reinterpret_cast<const float4*>(sOut);
#pragma unroll
        for (int i = 0; i < 3; ++i) {
            const int idx = tid + 256 * i;
            if (idx < 576) __stcs(o4 + idx, s4[idx]);
        }
    } else {
        const int cnt = (N - base) * 9;
        for (int i = tid; i < cnt; i += 256) out[(size_t)base * 9 + i] = sOut[i];
    }
}

extern "C" void kernel_launch(void* const* d_in, const int* in_sizes, int n_in,
                              void* d_out, int out_size) {
    const float* texc   = (const float*)d_in[0];
    const float* grid   = (const float*)d_in[1];
    const float* W0     = (const float*)d_in[2];
    const float* W1     = (const float*)d_in[3];
    const float* W2     = (const float*)d_in[4];
    const float* AABB   = (const float*)d_in[5];
    const float* minmax = (const float*)d_in[6];
    float* out = (float*)d_out;

    const int N = in_sizes[0] / 3;

    repack_pairs<<<(NPAIRS + 255u) / 256u, 256>>>(
        reinterpret_cast<const float2*>(grid));
    repack_records<<<(REC_CELLS + 255u) / 256u, 256>>>(
        reinterpret_cast<const float2*>(grid));
    prep_consts<<<1, 256>>>(W0, W1, W2, AABB, minmax);

    void* stagePtr = nullptr;
    cudaGetSymbolAddress(&stagePtr, gStage);
    cudaMemcpyToSymbolAsync(cc, stagePtr, sizeof(KConsts), 0,
                            cudaMemcpyDeviceToDevice, 0);

    const int blocks = (N + 255) / 256;
    fused_ngp_mlp<<<blocks, 256>>>(texc, out, N);
}